// round 1
// baseline (speedup 1.0000x reference)
#include <cuda_runtime.h>
#include <cstdint>
#include <cstddef>

// ---------------- scratch (no allocations allowed) ----------------
__device__ float  g_o1[8192 * 128];   // selu(fc1) activations, 4 MB
__device__ float  g_csum[128];
__device__ float  g_csumsq[128];
__device__ float  g_scale[128];       // bn fused scale
__device__ float  g_shift[128];       // bn fused shift
__device__ float  g_o[8192 * 2];      // final embedding
__device__ float  g_sq[8192];         // row squared norms
__device__ double g_denom;            // sum over upper triangle
__device__ float  g_inv;              // 1 / (2 * g_denom)

__device__ __forceinline__ float selu_f(float v) {
    const float sc = 1.0507009873554805f;
    const float al = 1.6732632423543772f;
    return v > 0.f ? sc * v : sc * al * expm1f(v);
}

// ---------------- kernel 0: zero accumulators ----------------
__global__ void k_init() {
    int t = threadIdx.x;
    if (t < 128) { g_csum[t] = 0.f; g_csumsq[t] = 0.f; }
    if (t == 0)  { g_denom = 0.0; }
}

// ---------------- kernel 1: o1 = selu(x @ W1^T + b1) ----------------
// M=8192, N=128, K=784.  64x128 tile per block, BK=16, 4x8 per thread.
__global__ __launch_bounds__(256) void k_gemm1(
    const float* __restrict__ x, const float* __restrict__ w,
    const float* __restrict__ bias)
{
    __shared__ float As[16][68];    // [k][m] transposed, padded
    __shared__ float Bs[16][132];   // [k][n] padded

    int t  = threadIdx.x;
    int tx = t & 15;       // col group (8 cols each)
    int ty = t >> 4;       // row group (4 rows each)
    int row0 = blockIdx.x * 64;

    float acc[4][8];
#pragma unroll
    for (int i = 0; i < 4; i++)
#pragma unroll
        for (int j = 0; j < 8; j++) acc[i][j] = 0.f;

    const int K = 784;
    for (int k0 = 0; k0 < K; k0 += 16) {
        // load A tile 64x16 (float4 along k, transpose into As[k][m])
        {
            int r  = t >> 2;          // 0..63
            int kk = (t & 3) * 4;     // 0,4,8,12
            float4 v = *(const float4*)&x[(size_t)(row0 + r) * 784 + k0 + kk];
            As[kk + 0][r] = v.x;
            As[kk + 1][r] = v.y;
            As[kk + 2][r] = v.z;
            As[kk + 3][r] = v.w;
        }
        // load B tile: Bs[k][n] = w[n][k],  16x128
        {
            int n  = t >> 1;          // 0..127
            int kk = (t & 1) * 8;     // 0 or 8
            float4 v0 = *(const float4*)&w[(size_t)n * 784 + k0 + kk];
            float4 v1 = *(const float4*)&w[(size_t)n * 784 + k0 + kk + 4];
            Bs[kk + 0][n] = v0.x; Bs[kk + 1][n] = v0.y;
            Bs[kk + 2][n] = v0.z; Bs[kk + 3][n] = v0.w;
            Bs[kk + 4][n] = v1.x; Bs[kk + 5][n] = v1.y;
            Bs[kk + 6][n] = v1.z; Bs[kk + 7][n] = v1.w;
        }
        __syncthreads();

#pragma unroll
        for (int k = 0; k < 16; k++) {
            float4 a  = *(const float4*)&As[k][ty * 4];
            float4 b0 = *(const float4*)&Bs[k][tx * 8];
            float4 b1 = *(const float4*)&Bs[k][tx * 8 + 4];
            float av[4] = {a.x, a.y, a.z, a.w};
            float bv[8] = {b0.x, b0.y, b0.z, b0.w, b1.x, b1.y, b1.z, b1.w};
#pragma unroll
            for (int i = 0; i < 4; i++)
#pragma unroll
                for (int j = 0; j < 8; j++)
                    acc[i][j] = fmaf(av[i], bv[j], acc[i][j]);
        }
        __syncthreads();
    }

    int col = tx * 8;
    float bias8[8];
#pragma unroll
    for (int j = 0; j < 8; j++) bias8[j] = bias[col + j];

#pragma unroll
    for (int i = 0; i < 4; i++) {
        int row = row0 + ty * 4 + i;
        float4 r0, r1;
        r0.x = selu_f(acc[i][0] + bias8[0]);
        r0.y = selu_f(acc[i][1] + bias8[1]);
        r0.z = selu_f(acc[i][2] + bias8[2]);
        r0.w = selu_f(acc[i][3] + bias8[3]);
        r1.x = selu_f(acc[i][4] + bias8[4]);
        r1.y = selu_f(acc[i][5] + bias8[5]);
        r1.z = selu_f(acc[i][6] + bias8[6]);
        r1.w = selu_f(acc[i][7] + bias8[7]);
        *(float4*)&g_o1[(size_t)row * 128 + col]     = r0;
        *(float4*)&g_o1[(size_t)row * 128 + col + 4] = r1;
    }
}

// ---------------- kernel 2: per-channel sum / sumsq partials ----------------
__global__ void k_stats() {
    int c  = threadIdx.x;                 // 128 channels
    int r0 = blockIdx.x * 128;            // 64 blocks x 128 rows
    float s = 0.f, ss = 0.f;
    for (int r = 0; r < 128; r++) {
        float v = g_o1[(size_t)(r0 + r) * 128 + c];
        s += v;
        ss = fmaf(v, v, ss);
    }
    atomicAdd(&g_csum[c], s);
    atomicAdd(&g_csumsq[c], ss);
}

// ---------------- kernel 3: finalize BN scale/shift ----------------
__global__ void k_stats_final(const float* __restrict__ gamma,
                              const float* __restrict__ beta) {
    int c = threadIdx.x;
    const float invn = 1.f / 8192.f;
    float mu  = g_csum[c] * invn;
    float var = g_csumsq[c] * invn - mu * mu;
    float rstd = rsqrtf(var + 1e-5f);
    float sc = rstd * gamma[c];
    g_scale[c] = sc;
    g_shift[c] = beta[c] - mu * sc;
}

// ---------------- kernel 4: o = selu(bn(o1) @ W2^T + b2), sq ----------------
__global__ __launch_bounds__(256) void k_fc2(
    const float* __restrict__ w2, const float* __restrict__ b2,
    float* __restrict__ o_tail)
{
    int gw   = (blockIdx.x * blockDim.x + threadIdx.x) >> 5;  // warp id = row
    int lane = threadIdx.x & 31;
    if (gw >= 8192) return;

    float a0 = 0.f, a1 = 0.f;
#pragma unroll
    for (int q = 0; q < 4; q++) {
        int c = lane + q * 32;
        float v = fmaf(g_o1[(size_t)gw * 128 + c], g_scale[c], g_shift[c]);
        a0 = fmaf(v, w2[c], a0);
        a1 = fmaf(v, w2[128 + c], a1);
    }
#pragma unroll
    for (int off = 16; off > 0; off >>= 1) {
        a0 += __shfl_xor_sync(0xffffffffu, a0, off);
        a1 += __shfl_xor_sync(0xffffffffu, a1, off);
    }
    if (lane == 0) {
        float y0 = selu_f(a0 + b2[0]);
        float y1 = selu_f(a1 + b2[1]);
        g_o[2 * gw]     = y0;
        g_o[2 * gw + 1] = y1;
        g_sq[gw] = fmaf(y1, y1, y0 * y0);
        o_tail[2 * gw]     = y0;
        o_tail[2 * gw + 1] = y1;
    }
}

// ---------------- kernel 5: denom = sum over upper triangle ----------------
// tile: 8 rows x 1024 cols, accumulate 1/(1+dis) where j > i
__global__ __launch_bounds__(256) void k_denom() {
    int bx = blockIdx.x;                 // 8 col tiles
    int by = blockIdx.y;                 // 1024 row tiles
    int c0base = bx * 1024;
    int i0 = by * 8;
    // skip tiles entirely at/below diagonal (no j > i inside)
    if (c0base + 1023 <= i0) return;

    __shared__ float sx[1024], sy[1024], ssq[1024];
    int t = threadIdx.x;
    {
        int c = c0base + t * 4;
        const float4* o4 = (const float4*)g_o;
        float4 va = o4[c >> 1];          // points c, c+1
        float4 vb = o4[(c >> 1) + 1];    // points c+2, c+3
        sx[t * 4 + 0] = va.x; sy[t * 4 + 0] = va.y;
        sx[t * 4 + 1] = va.z; sy[t * 4 + 1] = va.w;
        sx[t * 4 + 2] = vb.x; sy[t * 4 + 2] = vb.y;
        sx[t * 4 + 3] = vb.z; sy[t * 4 + 3] = vb.w;
        *(float4*)&ssq[t * 4] = *(const float4*)&g_sq[c];
    }
    __syncthreads();

    float lsum = 0.f;
#pragma unroll
    for (int r = 0; r < 8; r++) {
        int i = i0 + r;
        float xi = g_o[2 * i], yi = g_o[2 * i + 1], si = g_sq[i];
#pragma unroll
        for (int cc = 0; cc < 4; cc++) {
            int lc = t * 4 + cc;
            int j  = c0base + lc;
            if (j > i) {
                float dot = fmaf(yi, sy[lc], xi * sx[lc]);
                float w   = fmaf(-2.f, dot, si + ssq[lc]);
                w = fmaxf(w, 0.f) + 1.f;
                lsum += __fdividef(1.f, w);
            }
        }
    }

    __shared__ float red[256];
    red[t] = lsum;
    __syncthreads();
    for (int s = 128; s > 0; s >>= 1) {
        if (t < s) red[t] += red[t + s];
        __syncthreads();
    }
    if (t == 0) atomicAdd(&g_denom, (double)red[0]);
}

// ---------------- kernel 6: inv denom ----------------
__global__ void k_inv() {
    g_inv = (float)(1.0 / (2.0 * g_denom));
}

// ---------------- kernel 7: write qij ----------------
__global__ __launch_bounds__(256) void k_write(float* __restrict__ out) {
    int bx = blockIdx.x;                 // 8 col tiles of 1024
    int by = blockIdx.y;                 // 1024 row tiles of 8
    int c0base = bx * 1024;
    int i0 = by * 8;

    __shared__ float sx[1024], sy[1024], ssq[1024];
    int t = threadIdx.x;
    {
        int c = c0base + t * 4;
        const float4* o4 = (const float4*)g_o;
        float4 va = o4[c >> 1];
        float4 vb = o4[(c >> 1) + 1];
        sx[t * 4 + 0] = va.x; sy[t * 4 + 0] = va.y;
        sx[t * 4 + 1] = va.z; sy[t * 4 + 1] = va.w;
        sx[t * 4 + 2] = vb.x; sy[t * 4 + 2] = vb.y;
        sx[t * 4 + 3] = vb.z; sy[t * 4 + 3] = vb.w;
        *(float4*)&ssq[t * 4] = *(const float4*)&g_sq[c];
    }
    __syncthreads();

    float inv = g_inv;
    int lc0 = t * 4;

#pragma unroll
    for (int r = 0; r < 8; r++) {
        int i = i0 + r;
        float xi = g_o[2 * i], yi = g_o[2 * i + 1], si = g_sq[i];
        float4 q;
        {
            float dot = fmaf(yi, sy[lc0 + 0], xi * sx[lc0 + 0]);
            float w = fmaf(-2.f, dot, si + ssq[lc0 + 0]);
            q.x = __fdividef(inv, fmaxf(w, 0.f) + 1.f);
        }
        {
            float dot = fmaf(yi, sy[lc0 + 1], xi * sx[lc0 + 1]);
            float w = fmaf(-2.f, dot, si + ssq[lc0 + 1]);
            q.y = __fdividef(inv, fmaxf(w, 0.f) + 1.f);
        }
        {
            float dot = fmaf(yi, sy[lc0 + 2], xi * sx[lc0 + 2]);
            float w = fmaf(-2.f, dot, si + ssq[lc0 + 2]);
            q.z = __fdividef(inv, fmaxf(w, 0.f) + 1.f);
        }
        {
            float dot = fmaf(yi, sy[lc0 + 3], xi * sx[lc0 + 3]);
            float w = fmaf(-2.f, dot, si + ssq[lc0 + 3]);
            q.w = __fdividef(inv, fmaxf(w, 0.f) + 1.f);
        }
        // streaming store: qij is never re-read, keep it out of L2
        float4* dst = (float4*)&out[(size_t)i * 8192 + c0base + lc0];
        asm volatile("st.global.cs.v4.f32 [%0], {%1, %2, %3, %4};"
                     :: "l"(dst), "f"(q.x), "f"(q.y), "f"(q.z), "f"(q.w)
                     : "memory");
    }
}

// ---------------- launch ----------------
extern "C" void kernel_launch(void* const* d_in, const int* in_sizes, int n_in,
                              void* d_out, int out_size) {
    const float* x     = (const float*)d_in[0];
    const float* fc_w  = (const float*)d_in[1];
    const float* fc_b  = (const float*)d_in[2];
    const float* gamma = (const float*)d_in[3];
    const float* beta  = (const float*)d_in[4];
    const float* fc2_w = (const float*)d_in[5];
    const float* fc2_b = (const float*)d_in[6];
    float* out = (float*)d_out;
    // output layout: qij [8192*8192] then o [8192*2]
    float* o_tail = out + ((size_t)out_size - 8192 * 2);

    k_init<<<1, 256>>>();
    k_gemm1<<<128, 256>>>(x, fc_w, fc_b);
    k_stats<<<64, 128>>>();
    k_stats_final<<<1, 128>>>(gamma, beta);
    k_fc2<<<1024, 256>>>(fc2_w, fc2_b, o_tail);
    k_denom<<<dim3(8, 1024), 256>>>();
    k_inv<<<1, 1>>>();
    k_write<<<dim3(8, 1024), 256>>>(out);
}